// round 1
// baseline (speedup 1.0000x reference)
#include <cuda_runtime.h>

// KANLinear as one fused GEMM:
//   out[n,o] = sum_{i,j} A[n, i*9+j] * W[i*9+j, o] + bias[o]
// where for feature i of row n (xc = clip(x,-1,1)):
//   A[.., j<8] = chebyshev-like bases b0=1, b1=xc, b_j = 2*xc*b_{j-1} - 1
//   A[.., j=8] = silu(xc)
//   W[i*9+j, o] = (j<8) ? scale_spline[o,i]*coeff[o,i,j] : scale_base[o,i]
//   bias[o]    = sum_i base_bias[o,i]

#define IN_F   512
#define OUT_F  512
#define KB     8            // spline basis count
#define KE     9            // expanded per-feature (8 spline + 1 silu)
#define NROWS  8192
#define KTOT   (IN_F * KE)  // 4608

// -------- device scratch (static allocation: allowed) --------
__device__ float g_W[KTOT * OUT_F];   // [kk][o], o contiguous  (9.44 MB)
__device__ float g_bias[OUT_F];

// -------- weight expansion --------
__global__ void expand_w_kernel(const float* __restrict__ coeff,
                                const float* __restrict__ scale_base,
                                const float* __restrict__ scale_spline) {
    int idx = blockIdx.x * blockDim.x + threadIdx.x;
    if (idx >= KTOT * OUT_F) return;
    int o  = idx & (OUT_F - 1);
    int kk = idx >> 9;           // OUT_F = 512
    int i  = kk / KE;
    int j  = kk - i * KE;
    float v;
    if (j < KB) v = scale_spline[o * IN_F + i] * coeff[(o * IN_F + i) * KB + j];
    else        v = scale_base[o * IN_F + i];
    g_W[idx] = v;
}

// -------- bias reduction --------
__global__ void bias_kernel(const float* __restrict__ base_bias) {
    __shared__ float red[256];
    int o = blockIdx.x;
    float s = 0.f;
    for (int i = threadIdx.x; i < IN_F; i += 256) s += base_bias[o * IN_F + i];
    red[threadIdx.x] = s;
    __syncthreads();
    for (int off = 128; off > 0; off >>= 1) {
        if (threadIdx.x < off) red[threadIdx.x] += red[threadIdx.x + off];
        __syncthreads();
    }
    if (threadIdx.x == 0) g_bias[o] = red[0];
}

// -------- fused GEMM: A generated on the fly from x --------
// BM=128, BN=128, 256 threads, 8x8 micro-tile. K-chunk = 4 features = 36 kk.
#define BM 128
#define BN 128
#define IC 4
#define BK (IC * KE)   // 36

__global__ void __launch_bounds__(256, 2) kan_gemm_kernel(
    const float* __restrict__ x, float* __restrict__ out)
{
    __shared__ float As[BK][BM];   // 18 KB, kk-major
    __shared__ float Bs[BK][BN];   // 18 KB

    const int tid  = threadIdx.x;
    const int tx   = tid & 15;     // 0..15 -> output cols
    const int ty   = tid >> 4;     // 0..15 -> output rows
    const int row0 = blockIdx.x * BM;
    const int col0 = blockIdx.y * BN;

    float acc[8][8];
#pragma unroll
    for (int i = 0; i < 8; i++)
#pragma unroll
        for (int j = 0; j < 8; j++) acc[i][j] = 0.f;

    // A-expansion thread mapping: 256 threads cover 128 rows x 4 features
    const int ar = tid & 127;        // row within tile
    const int ac = (tid >> 7) * 2;   // feature pair: 0 or 2

    for (int ic = 0; ic < IN_F; ic += IC) {
        // ---- generate A tile (basis expansion) ----
        {
            const float2 xv = *reinterpret_cast<const float2*>(
                &x[(size_t)(row0 + ar) * IN_F + ic + ac]);
            float xs[2] = {xv.x, xv.y};
#pragma unroll
            for (int c = 0; c < 2; c++) {
                const int f = ac + c;
                float xc = fminf(fmaxf(xs[c], -1.f), 1.f);
                As[f * KE + 0][ar] = 1.f;
                As[f * KE + 1][ar] = xc;
                float prev = xc;
#pragma unroll
                for (int j = 2; j < KB; j++) {
                    prev = 2.f * xc * prev - 1.f;
                    As[f * KE + j][ar] = prev;
                }
                float sig = 1.f / (1.f + __expf(-xc));
                As[f * KE + KB][ar] = xc * sig;   // silu
            }
        }
        // ---- load B tile (coalesced) ----
#pragma unroll
        for (int t = 0; t < (BK * BN) / 256; t++) {
            int idx = tid + t * 256;
            int kk = idx >> 7;         // /128
            int c  = idx & 127;
            Bs[kk][c] = g_W[(size_t)(ic * KE + kk) * OUT_F + col0 + c];
        }
        __syncthreads();

        // ---- compute ----
#pragma unroll 6
        for (int kk = 0; kk < BK; kk++) {
            float a[8], b[8];
            *reinterpret_cast<float4*>(&a[0]) = *reinterpret_cast<float4*>(&As[kk][ty * 4]);
            *reinterpret_cast<float4*>(&a[4]) = *reinterpret_cast<float4*>(&As[kk][64 + ty * 4]);
            *reinterpret_cast<float4*>(&b[0]) = *reinterpret_cast<float4*>(&Bs[kk][tx * 4]);
            *reinterpret_cast<float4*>(&b[4]) = *reinterpret_cast<float4*>(&Bs[kk][64 + tx * 4]);
#pragma unroll
            for (int i = 0; i < 8; i++)
#pragma unroll
                for (int j = 0; j < 8; j++)
                    acc[i][j] = fmaf(a[i], b[j], acc[i][j]);
        }
        __syncthreads();
    }

    // ---- epilogue: add bias, write out ----
    float bb[8];
    *reinterpret_cast<float4*>(&bb[0]) = *reinterpret_cast<const float4*>(&g_bias[col0 + tx * 4]);
    *reinterpret_cast<float4*>(&bb[4]) = *reinterpret_cast<const float4*>(&g_bias[col0 + 64 + tx * 4]);

#pragma unroll
    for (int i = 0; i < 8; i++) {
        const int r = row0 + ((i < 4) ? (ty * 4 + i) : (64 + ty * 4 + (i - 4)));
        float4 v0, v1;
        v0.x = acc[i][0] + bb[0]; v0.y = acc[i][1] + bb[1];
        v0.z = acc[i][2] + bb[2]; v0.w = acc[i][3] + bb[3];
        v1.x = acc[i][4] + bb[4]; v1.y = acc[i][5] + bb[5];
        v1.z = acc[i][6] + bb[6]; v1.w = acc[i][7] + bb[7];
        *reinterpret_cast<float4*>(&out[(size_t)r * OUT_F + col0 + tx * 4])      = v0;
        *reinterpret_cast<float4*>(&out[(size_t)r * OUT_F + col0 + 64 + tx * 4]) = v1;
    }
}

extern "C" void kernel_launch(void* const* d_in, const int* in_sizes, int n_in,
                              void* d_out, int out_size) {
    const float* x            = (const float*)d_in[0];  // (8,1024,512)
    const float* coeff        = (const float*)d_in[1];  // (512,512,8)
    const float* scale_base   = (const float*)d_in[2];  // (512,512)
    const float* scale_spline = (const float*)d_in[3];  // (512,512)
    const float* base_bias    = (const float*)d_in[4];  // (512,512)
    float* out = (float*)d_out;                          // (8,1024,512)

    (void)in_sizes; (void)n_in; (void)out_size;

    // 1) expand weights into g_W  [4608 x 512]
    {
        int total = KTOT * OUT_F;
        expand_w_kernel<<<(total + 255) / 256, 256>>>(coeff, scale_base, scale_spline);
    }
    // 2) bias sums
    bias_kernel<<<OUT_F, 256>>>(base_bias);

    // 3) fused GEMM
    dim3 grid(NROWS / BM, OUT_F / BN);   // 64 x 4
    kan_gemm_kernel<<<grid, 256>>>(x, out);
}

// round 3
// speedup vs baseline: 2.7237x; 2.7237x over previous
#include <cuda_runtime.h>
#include <cstdint>

// KANLinear as one fused tf32 mma.sync GEMM (K reduced to 4096 by folding the
// constant basis j=0 into the bias):
//   out[n,o] = sum_{i,j'} A[n, i*8+j'] * W[o, i*8+j'] + bias[o]
//   A[.., j'<7] = T_{j'+1}(xc) via b1=xc, b_{t+1}=2*xc*b_t - 1   (xc=clip(x,-1,1))
//   A[.., j'=7] = silu(xc)
//   W[o, i*8+j'] = (j'<7) ? scale_spline[o,i]*coeff[o,i,j'+1] : scale_base[o,i]
//   bias[o] = sum_i base_bias[o,i] + scale_spline[o,i]*coeff[o,i,0]

#define IN_F   512
#define OUT_F  512
#define NROWS  8192
#define KE     8
#define KTOT   (IN_F * KE)     // 4096
#define BM     128
#define BN     128
#define BK     32              // 4 features per chunk
#define NCHUNK (KTOT / BK)     // 128

// g_W stored in mma-B-fragment order: [c][nb][ks][lane][2] floats
//   c = chunk, nb = o>>3, ks = k_in>>3 (feature-in-chunk), lane = (o&7)*4 + (k8&3),
//   reg = k8>>2  (b0 = k=t, b1 = k=t+4)
__device__ float g_W[(size_t)NCHUNK * 64 * 256];   // 8.39 MB
__device__ float g_bias[OUT_F];

// -------- helpers --------
__device__ __forceinline__ uint32_t smem_u32(const void* p) {
    uint32_t a;
    asm("{ .reg .u64 t; cvta.to.shared.u64 t, %1; cvt.u32.u64 %0, t; }" : "=r"(a) : "l"(p));
    return a;
}
__device__ __forceinline__ float to_tf32(float v) {
    float r;
    asm("cvt.rna.tf32.f32 %0, %1;" : "=f"(r) : "f"(v));
    return r;
}
#define CP_ASYNC16(dst, src) \
    asm volatile("cp.async.cg.shared.global [%0], [%1], 16;" :: "r"(dst), "l"(src))
#define CP_COMMIT() asm volatile("cp.async.commit_group;" ::: "memory")
#define CP_WAIT0()  asm volatile("cp.async.wait_group 0;" ::: "memory")

__device__ __forceinline__ void mma_tf32(float* d, const float4& a, const float2& b) {
    // A fragment SMEM slot order: [ (g,t), (g,t+4), (g+8,t), (g+8,t+4) ]
    // mma operand order {a0,a1,a2,a3} = {(g,t),(g+8,t),(g,t+4),(g+8,t+4)} -> x,z,y,w
    asm volatile(
        "mma.sync.aligned.m16n8k8.row.col.f32.tf32.tf32.f32 "
        "{%0,%1,%2,%3}, {%4,%5,%6,%7}, {%8,%9}, {%0,%1,%2,%3};"
        : "+f"(d[0]), "+f"(d[1]), "+f"(d[2]), "+f"(d[3])
        : "r"(__float_as_uint(a.x)), "r"(__float_as_uint(a.z)),
          "r"(__float_as_uint(a.y)), "r"(__float_as_uint(a.w)),
          "r"(__float_as_uint(b.x)), "r"(__float_as_uint(b.y)));
}

// -------- weight expansion into fragment layout --------
__global__ void expand_w_kernel(const float* __restrict__ coeff,
                                const float* __restrict__ scale_base,
                                const float* __restrict__ scale_spline) {
    int kk = blockIdx.x * blockDim.x + threadIdx.x;   // 0..4095
    int o  = blockIdx.y;
    int i  = kk >> 3;
    int jp = kk & 7;
    float v;
    if (jp < 7) v = scale_spline[o * IN_F + i] * coeff[(o * IN_F + i) * 8 + jp + 1];
    else        v = scale_base[o * IN_F + i];
    int c  = kk >> 5;
    int ki = kk & 31;
    int ks = ki >> 3;
    int k8 = ki & 7;
    int t  = k8 & 3, reg = k8 >> 2;
    int nb = o >> 3, g = o & 7;
    int lane = g * 4 + t;
    g_W[(((size_t)c * 64 + nb) * 4 + ks) * 64 + lane * 2 + reg] = to_tf32(v);
}

// -------- bias (base_bias rowsum + folded j=0 spline term) --------
__global__ void bias_kernel(const float* __restrict__ base_bias,
                            const float* __restrict__ coeff,
                            const float* __restrict__ scale_spline) {
    __shared__ float red[256];
    int o = blockIdx.x;
    float s = 0.f;
    for (int i = threadIdx.x; i < IN_F; i += 256) {
        s += base_bias[o * IN_F + i]
           + scale_spline[o * IN_F + i] * coeff[(o * IN_F + i) * 8 + 0];
    }
    red[threadIdx.x] = s;
    __syncthreads();
    for (int off = 128; off > 0; off >>= 1) {
        if (threadIdx.x < off) red[threadIdx.x] += red[threadIdx.x + off];
        __syncthreads();
    }
    if (threadIdx.x == 0) g_bias[o] = red[0];
}

// -------- GEMM --------
// SMEM: A0 A1 B0 B1, each 4096 floats (16 KB). A fragment layout:
//   [mt 8][ks 4][lane 32][slot 4], slot = 2*(m_in>=8) + (k8>=4)
__device__ __forceinline__ void gen_a(float* Abuf, float2 xv, int ar, int ah) {
    const int mt = ar >> 4, m_in = ar & 15;
    const int slot_base = (m_in >= 8) ? 2 : 0;
    const int lane_row = (m_in & 7) * 4;
    float xs[2] = {xv.x, xv.y};
#pragma unroll
    for (int f = 0; f < 2; f++) {
        float xc = fminf(fmaxf(xs[f], -1.f), 1.f);
        float vals[8];
        float b = xc;
        vals[0] = b;
#pragma unroll
        for (int t = 1; t < 7; t++) { b = 2.f * xc * b - 1.f; vals[t] = b; }
        vals[7] = xc / (1.f + __expf(-xc));   // silu
#pragma unroll
        for (int t = 0; t < 8; t++) vals[t] = to_tf32(vals[t]);
        const int ks = ah * 2 + f;
        float* base = Abuf + (size_t)(mt * 4 + ks) * 128;
#pragma unroll
        for (int t = 0; t < 4; t++) {
            float2 v2 = make_float2(vals[t], vals[t + 4]);
            *(float2*)(base + (lane_row + t) * 4 + slot_base) = v2;
        }
    }
}

__device__ __forceinline__ void cp_b(int c, uint32_t dst_s, int tid, int col0) {
    const float* src = g_W + ((size_t)c * 64 + (col0 >> 3)) * 256 + tid * 4;
    uint32_t d = dst_s + (uint32_t)tid * 16;
#pragma unroll
    for (int q = 0; q < 4; q++)
        CP_ASYNC16(d + q * 4096u, src + q * 1024);
}

__device__ __forceinline__ void do_mma(const float* Abuf, const float* Bbuf,
                                       float acc[2][8][4], int wm, int wn, int lane) {
#pragma unroll
    for (int ks = 0; ks < 4; ks++) {
        float4 a[2];
        float2 b[8];
#pragma unroll
        for (int i = 0; i < 2; i++)
            a[i] = *(const float4*)(Abuf + (size_t)(((wm * 2 + i) * 4 + ks) * 32 + lane) * 4);
#pragma unroll
        for (int j = 0; j < 8; j++)
            b[j] = *(const float2*)(Bbuf + (size_t)(((wn * 8 + j) * 4 + ks) * 32 + lane) * 2);
#pragma unroll
        for (int i = 0; i < 2; i++)
#pragma unroll
            for (int j = 0; j < 8; j++)
                mma_tf32(acc[i][j], a[i], b[j]);
    }
}

__global__ void __launch_bounds__(256, 2) kan_mma_kernel(
    const float* __restrict__ x, float* __restrict__ out)
{
    extern __shared__ float smem[];
    float* Ab[2] = { smem,        smem + 4096 };
    float* Bb[2] = { smem + 8192, smem + 12288 };
    const uint32_t sb = smem_u32(smem);
    const uint32_t bsmem[2] = { sb + 8192u * 4u, sb + 12288u * 4u };

    const int tid = threadIdx.x;
    const int wid = tid >> 5, lane = tid & 31;
    const int wm = wid & 3, wn = wid >> 2;
    const int row0 = blockIdx.x * BM;
    const int col0 = blockIdx.y * BN;

    const int ar = tid >> 1, ah = tid & 1;
    const float* xrow = x + (size_t)(row0 + ar) * IN_F + ah * 2;

    float acc[2][8][4];
#pragma unroll
    for (int i = 0; i < 2; i++)
#pragma unroll
        for (int j = 0; j < 8; j++)
#pragma unroll
            for (int q = 0; q < 4; q++) acc[i][j][q] = 0.f;

    // prologue: chunk 0
    cp_b(0, bsmem[0], tid, col0);
    CP_COMMIT();
    gen_a(Ab[0], *(const float2*)(xrow), ar, ah);
    CP_WAIT0();
    __syncthreads();

    for (int c = 0; c < NCHUNK; c++) {
        const int cur = c & 1;
        const bool has = (c + 1 < NCHUNK);
        float2 xn;
        if (has) {
            cp_b(c + 1, bsmem[cur ^ 1], tid, col0);
            CP_COMMIT();
            xn = *(const float2*)(xrow + (c + 1) * 4);  // LDG issued early
        }
        do_mma(Ab[cur], Bb[cur], acc, wm, wn, lane);
        if (has) {
            gen_a(Ab[cur ^ 1], xn, ar, ah);
            CP_WAIT0();
        }
        __syncthreads();
    }

    // epilogue: add bias, write (float2 stores)
    const int g = lane >> 2, t2 = (lane & 3) * 2;
#pragma unroll
    for (int j = 0; j < 8; j++) {
        const int col = col0 + wn * 64 + j * 8 + t2;
        const float2 bs = *(const float2*)&g_bias[col];
#pragma unroll
        for (int i = 0; i < 2; i++) {
            const int r = row0 + wm * 32 + i * 16 + g;
            float2 v0 = make_float2(acc[i][j][0] + bs.x, acc[i][j][1] + bs.y);
            float2 v1 = make_float2(acc[i][j][2] + bs.x, acc[i][j][3] + bs.y);
            *(float2*)(out + (size_t)r * OUT_F + col)       = v0;
            *(float2*)(out + (size_t)(r + 8) * OUT_F + col) = v1;
        }
    }
}

extern "C" void kernel_launch(void* const* d_in, const int* in_sizes, int n_in,
                              void* d_out, int out_size) {
    const float* x            = (const float*)d_in[0];
    const float* coeff        = (const float*)d_in[1];
    const float* scale_base   = (const float*)d_in[2];
    const float* scale_spline = (const float*)d_in[3];
    const float* base_bias    = (const float*)d_in[4];
    float* out = (float*)d_out;
    (void)in_sizes; (void)n_in; (void)out_size;

    static bool attr_set = false;
    if (!attr_set) {
        cudaFuncSetAttribute(kan_mma_kernel,
                             cudaFuncAttributeMaxDynamicSharedMemorySize, 65536);
        attr_set = true;
    }

    dim3 eg(KTOT / 256, OUT_F);
    expand_w_kernel<<<eg, 256>>>(coeff, scale_base, scale_spline);
    bias_kernel<<<OUT_F, 256>>>(base_bias, coeff, scale_spline);

    dim3 grid(NROWS / BM, OUT_F / BN);   // 64 x 4
    kan_mma_kernel<<<grid, 256, 65536>>>(x, out);
}

// round 4
// speedup vs baseline: 3.5456x; 1.3017x over previous
#include <cuda_runtime.h>
#include <cuda_fp16.h>
#include <cstdint>

// KANLinear as one fused fp16 mma.sync GEMM (fp16 mantissa == tf32 mantissa,
// so same precision as the tf32 round at 2x the legacy-HMMA rate).
// K reduced to 4096 by folding constant basis j=0 into the bias:
//   out[n,o] = sum_{i,j'} A[n, i*8+j'] * W[o, i*8+j'] + bias[o]
//   A[.., j'<7] = T_{j'+1}(xc), b1=xc, b_{t+1}=2*xc*b_t - 1 (xc=clip(x,-1,1))
//   A[.., j'=7] = silu(xc)
//   W[o, i*8+j'] = (j'<7) ? scale_spline[o,i]*coeff[o,i,j'+1] : scale_base[o,i]
//   bias[o] = sum_i base_bias[o,i] + scale_spline[o,i]*coeff[o,i,0]

#define IN_F   512
#define OUT_F  512
#define NROWS  8192
#define KTOT   4096
#define BM     128
#define BN     128
#define BK     64              // 8 features per chunk
#define NCHUNK (KTOT / BK)     // 64

// g_W in mma-B fragment order, 2 n8-groups packed per 16B for LDS.128:
//   [c][nb2][ks][lane][8 halves]; halves: {b0,b1 of even nb, b0,b1 of odd nb}
__device__ __half g_W[(size_t)NCHUNK * 32 * 1024];   // 4 MB
__device__ float  g_bias[OUT_F];

// -------- helpers --------
__device__ __forceinline__ uint32_t smem_u32(const void* p) {
    uint32_t a;
    asm("{ .reg .u64 t; cvta.to.shared.u64 t, %1; cvt.u32.u64 %0, t; }" : "=r"(a) : "l"(p));
    return a;
}
#define CP_ASYNC16(dst, src) \
    asm volatile("cp.async.cg.shared.global [%0], [%1], 16;" :: "r"(dst), "l"(src))
#define CP_COMMIT() asm volatile("cp.async.commit_group;" ::: "memory")
#define CP_WAIT0()  asm volatile("cp.async.wait_group 0;" ::: "memory")

__device__ __forceinline__ void mma_fp16(float* d, uint32_t a0, uint32_t a1,
                                         uint32_t a2, uint32_t a3,
                                         uint32_t b0, uint32_t b1) {
    asm volatile(
        "mma.sync.aligned.m16n8k16.row.col.f32.f16.f16.f32 "
        "{%0,%1,%2,%3}, {%4,%5,%6,%7}, {%8,%9}, {%0,%1,%2,%3};"
        : "+f"(d[0]), "+f"(d[1]), "+f"(d[2]), "+f"(d[3])
        : "r"(a0), "r"(a1), "r"(a2), "r"(a3), "r"(b0), "r"(b1));
}

// -------- weight expansion into fp16 fragment layout --------
__global__ void expand_w_kernel(const float* __restrict__ coeff,
                                const float* __restrict__ scale_base,
                                const float* __restrict__ scale_spline) {
    int kk2 = blockIdx.x * blockDim.x + threadIdx.x;   // 0..2047
    int o   = blockIdx.y;
    int kk  = kk2 * 2;
    int i   = kk >> 3;
    int jp  = kk & 7;                                  // even: 0,2,4,6
    const float* cb = coeff + ((size_t)o * IN_F + i) * 8;
    float ss = scale_spline[o * IN_F + i];
    float v0 = ss * cb[jp + 1];
    float v1 = (jp + 1 < 7) ? ss * cb[jp + 2] : scale_base[o * IN_F + i];
    int c = kk >> 6, k_in = kk & 63, ks = k_in >> 4, kk16 = k_in & 15;
    int rb = kk16 >> 3, t = (kk16 & 7) >> 1;
    int nb = o >> 3, g = o & 7, lane = g * 4 + t;
    size_t idx2 = ((((size_t)c * 32 + (nb >> 1)) * 4 + ks) * 32 + lane) * 4
                + (nb & 1) * 2 + rb;
    ((__half2*)g_W)[idx2] = __floats2half2_rn(v0, v1);
}

// -------- bias (base_bias rowsum + folded j=0 spline term) --------
__global__ void bias_kernel(const float* __restrict__ base_bias,
                            const float* __restrict__ coeff,
                            const float* __restrict__ scale_spline) {
    __shared__ float red[256];
    int o = blockIdx.x;
    float s = 0.f;
    for (int i = threadIdx.x; i < IN_F; i += 256) {
        s += base_bias[o * IN_F + i]
           + scale_spline[o * IN_F + i] * coeff[((size_t)o * IN_F + i) * 8 + 0];
    }
    red[threadIdx.x] = s;
    __syncthreads();
    for (int off = 128; off > 0; off >>= 1) {
        if (threadIdx.x < off) red[threadIdx.x] += red[threadIdx.x + off];
        __syncthreads();
    }
    if (threadIdx.x == 0) g_bias[o] = red[0];
}

// -------- GEMM --------
// SMEM (bytes): A0 [0,16K) A1 [16K,32K) B0 [32K,48K) B1 [48K,64K)
// A fragment layout: [mt 8][ks 4][lane 32][a0 a1 a2 a3 as half2] (16B/lane)
// B fragment layout: [nb2 8][ks 4][lane 32][b0e b1e b0o b1o]     (16B/lane)

__device__ __forceinline__ void gen_a(__half2* Abuf, float4 xv, int ar, int ah) {
    const int mt = ar >> 4, m = ar & 15, g = m & 7, hi = m >> 3;
    const int rot = m >> 1;            // STS bank-conflict rotation
    float xs[4] = {xv.x, xv.y, xv.z, xv.w};
#pragma unroll
    for (int fl = 0; fl < 4; fl++) {
        float xc = fminf(fmaxf(xs[fl], -1.f), 1.f);
        float vals[8];
        float b = xc;
        vals[0] = b;
#pragma unroll
        for (int t = 1; t < 7; t++) { b = 2.f * xc * b - 1.f; vals[t] = b; }
        vals[7] = xc / (1.f + __expf(-xc));   // silu
        const int ks  = (ah * 4 + fl) >> 1;
        const int reg = (fl & 1) * 2 + hi;    // a0/a1 (lo k8) or a2/a3 (hi k8)
        __half2* base = Abuf + (size_t)((mt * 4 + ks) * 32) * 4 + reg;
#pragma unroll
        for (int t0 = 0; t0 < 4; t0++) {
            int tp = (t0 + rot) & 3;
            base[(g * 4 + tp) * 4] = __floats2half2_rn(vals[2 * tp], vals[2 * tp + 1]);
        }
    }
}

__device__ __forceinline__ void cp_b(int c, uint32_t dst, int tid, int col0) {
    const __half* src = g_W + ((size_t)c * 32 + (col0 >> 4)) * 1024 + tid * 8;
    uint32_t d = dst + (uint32_t)tid * 16;
#pragma unroll
    for (int q = 0; q < 4; q++)
        CP_ASYNC16(d + q * 4096u, src + q * 2048);
}

__device__ __forceinline__ void do_mma(const uint4* Asm, const uint4* Bsm,
                                       float acc[2][8][4], int wm, int wn, int lane) {
#pragma unroll
    for (int ks = 0; ks < 4; ks++) {
        uint4 a[2];
#pragma unroll
        for (int i = 0; i < 2; i++)
            a[i] = Asm[((wm * 2 + i) * 4 + ks) * 32 + lane];
#pragma unroll
        for (int j2 = 0; j2 < 4; j2++) {
            uint4 bb = Bsm[((wn * 4 + j2) * 4 + ks) * 32 + lane];
#pragma unroll
            for (int i = 0; i < 2; i++) {
                mma_fp16(acc[i][j2 * 2 + 0], a[i].x, a[i].y, a[i].z, a[i].w, bb.x, bb.y);
                mma_fp16(acc[i][j2 * 2 + 1], a[i].x, a[i].y, a[i].z, a[i].w, bb.z, bb.w);
            }
        }
    }
}

__global__ void __launch_bounds__(256, 2) kan_mma_kernel(
    const float* __restrict__ x, float* __restrict__ out)
{
    extern __shared__ char smem[];
    __half2* Ab[2] = { (__half2*)smem, (__half2*)(smem + 16384) };
    const uint4* As[2] = { (const uint4*)smem, (const uint4*)(smem + 16384) };
    const uint4* Bs[2] = { (const uint4*)(smem + 32768), (const uint4*)(smem + 49152) };
    const uint32_t sb = smem_u32(smem);
    const uint32_t bsm[2] = { sb + 32768u, sb + 49152u };

    const int tid = threadIdx.x;
    const int wid = tid >> 5, lane = tid & 31;
    const int wm = wid & 3, wn = wid >> 2;
    const int row0 = blockIdx.x * BM;
    const int col0 = blockIdx.y * BN;

    const int ar = tid >> 1, ah = tid & 1;
    const float* xrow = x + (size_t)(row0 + ar) * IN_F + ah * 4;

    float acc[2][8][4];
#pragma unroll
    for (int i = 0; i < 2; i++)
#pragma unroll
        for (int j = 0; j < 8; j++)
#pragma unroll
            for (int q = 0; q < 4; q++) acc[i][j][q] = 0.f;

    // prologue: chunk 0
    cp_b(0, bsm[0], tid, col0);
    CP_COMMIT();
    gen_a(Ab[0], *(const float4*)xrow, ar, ah);
    CP_WAIT0();
    __syncthreads();

    for (int c = 0; c < NCHUNK; c++) {
        const int cur = c & 1;
        const bool has = (c + 1 < NCHUNK);
        float4 xn;
        if (has) {
            cp_b(c + 1, bsm[cur ^ 1], tid, col0);
            CP_COMMIT();
            xn = *(const float4*)(xrow + (c + 1) * 8);   // early LDG
        }
        do_mma(As[cur], Bs[cur], acc, wm, wn, lane);
        if (has) {
            gen_a(Ab[cur ^ 1], xn, ar, ah);
            CP_WAIT0();
        }
        __syncthreads();
    }

    // epilogue: add bias, float2 stores
    const int g = lane >> 2, t2 = (lane & 3) * 2;
#pragma unroll
    for (int j = 0; j < 8; j++) {
        const int col = col0 + wn * 64 + j * 8 + t2;
        const float2 bs = *(const float2*)&g_bias[col];
#pragma unroll
        for (int i = 0; i < 2; i++) {
            const int r = row0 + wm * 32 + i * 16 + g;
            float2 v0 = make_float2(acc[i][j][0] + bs.x, acc[i][j][1] + bs.y);
            float2 v1 = make_float2(acc[i][j][2] + bs.x, acc[i][j][3] + bs.y);
            *(float2*)(out + (size_t)r * OUT_F + col)       = v0;
            *(float2*)(out + (size_t)(r + 8) * OUT_F + col) = v1;
        }
    }
}

extern "C" void kernel_launch(void* const* d_in, const int* in_sizes, int n_in,
                              void* d_out, int out_size) {
    const float* x            = (const float*)d_in[0];
    const float* coeff        = (const float*)d_in[1];
    const float* scale_base   = (const float*)d_in[2];
    const float* scale_spline = (const float*)d_in[3];
    const float* base_bias    = (const float*)d_in[4];
    float* out = (float*)d_out;
    (void)in_sizes; (void)n_in; (void)out_size;

    static bool attr_set = false;
    if (!attr_set) {
        cudaFuncSetAttribute(kan_mma_kernel,
                             cudaFuncAttributeMaxDynamicSharedMemorySize, 65536);
        attr_set = true;
    }

    dim3 eg((KTOT / 2) / 256, OUT_F);
    expand_w_kernel<<<eg, 256>>>(coeff, scale_base, scale_spline);
    bias_kernel<<<OUT_F, 256>>>(base_bias, coeff, scale_spline);

    dim3 grid(NROWS / BM, OUT_F / BN);   // 64 x 4
    kan_mma_kernel<<<grid, 256, 65536>>>(x, out);
}

// round 6
// speedup vs baseline: 5.5534x; 1.5663x over previous
#include <cuda_runtime.h>
#include <cuda_fp16.h>
#include <cstdint>

// KANLinear as one fused fp16 mma.sync GEMM, 3-stage cp.async pipeline.
// K = 4096 (constant basis j=0 folded into bias):
//   out[n,o] = sum_{i,j'} A[n, i*8+j'] * W[o, i*8+j'] + bias[o]
//   A[.., j'<7] = T_{j'+1}(xc), b1=xc, b_{t+1}=2*xc*b_t - 1 (xc=clip(x,-1,1))
//   A[.., j'=7] = silu(xc)
//   W[o, i*8+j'] = (j'<7) ? scale_spline[o,i]*coeff[o,i,j'+1] : scale_base[o,i]
//   bias[o] = sum_i base_bias[o,i] + scale_spline[o,i]*coeff[o,i,0]

#define IN_F   512
#define OUT_F  512
#define NROWS  8192
#define KTOT   4096
#define BM     128
#define BN     128
#define BK     64
#define NCHUNK (KTOT / BK)     // 64
#define NSTAGE 3

// g_W in mma-B fragment order, 2 n8-groups packed per 16B for LDS.128:
//   [c][nb2][ks][lane][8 halves]; halves: {b0,b1 of even nb, b0,b1 of odd nb}
__device__ __half g_W[(size_t)NCHUNK * 32 * 1024];   // 4 MB
__device__ float  g_bias[OUT_F];

// -------- helpers --------
__device__ __forceinline__ uint32_t smem_u32(const void* p) {
    uint32_t a;
    asm("{ .reg .u64 t; cvta.to.shared.u64 t, %1; cvt.u32.u64 %0, t; }" : "=r"(a) : "l"(p));
    return a;
}
#define CP_ASYNC16(dst, src) \
    asm volatile("cp.async.cg.shared.global [%0], [%1], 16;" :: "r"(dst), "l"(src))
#define CP_COMMIT()  asm volatile("cp.async.commit_group;" ::: "memory")
#define CP_WAIT(n)   asm volatile("cp.async.wait_group %0;" :: "n"(n) : "memory")

__device__ __forceinline__ void mma_fp16(float* d, uint32_t a0, uint32_t a1,
                                         uint32_t a2, uint32_t a3,
                                         uint32_t b0, uint32_t b1) {
    asm volatile(
        "mma.sync.aligned.m16n8k16.row.col.f32.f16.f16.f32 "
        "{%0,%1,%2,%3}, {%4,%5,%6,%7}, {%8,%9}, {%0,%1,%2,%3};"
        : "+f"(d[0]), "+f"(d[1]), "+f"(d[2]), "+f"(d[3])
        : "r"(a0), "r"(a1), "r"(a2), "r"(a3), "r"(b0), "r"(b1));
}

// -------- weight expansion into fp16 fragment layout --------
__global__ void expand_w_kernel(const float* __restrict__ coeff,
                                const float* __restrict__ scale_base,
                                const float* __restrict__ scale_spline) {
    int kk2 = blockIdx.x * blockDim.x + threadIdx.x;   // 0..2047
    int o   = blockIdx.y;
    int kk  = kk2 * 2;
    int i   = kk >> 3;
    int jp  = kk & 7;                                  // even: 0,2,4,6
    const float* cb = coeff + ((size_t)o * IN_F + i) * 8;
    float ss = scale_spline[o * IN_F + i];
    float v0 = ss * cb[jp + 1];
    float v1 = (jp + 1 < 7) ? ss * cb[jp + 2] : scale_base[o * IN_F + i];
    int c = kk >> 6, k_in = kk & 63, ks = k_in >> 4, kk16 = k_in & 15;
    int rb = kk16 >> 3, t = (kk16 & 7) >> 1;
    int nb = o >> 3, g = o & 7, lane = g * 4 + t;
    size_t idx2 = ((((size_t)c * 32 + (nb >> 1)) * 4 + ks) * 32 + lane) * 4
                + (nb & 1) * 2 + rb;
    ((__half2*)g_W)[idx2] = __floats2half2_rn(v0, v1);
}

// -------- bias (base_bias rowsum + folded j=0 spline term) --------
__global__ void bias_kernel(const float* __restrict__ base_bias,
                            const float* __restrict__ coeff,
                            const float* __restrict__ scale_spline) {
    __shared__ float red[256];
    int o = blockIdx.x;
    float s = 0.f;
    for (int i = threadIdx.x; i < IN_F; i += 256) {
        s += base_bias[o * IN_F + i]
           + scale_spline[o * IN_F + i] * coeff[((size_t)o * IN_F + i) * 8 + 0];
    }
    red[threadIdx.x] = s;
    __syncthreads();
    for (int off = 128; off > 0; off >>= 1) {
        if (threadIdx.x < off) red[threadIdx.x] += red[threadIdx.x + off];
        __syncthreads();
    }
    if (threadIdx.x == 0) g_bias[o] = red[0];
}

// -------- GEMM --------
// A buffer: [mt 8][ks 4] rows of 33*16B = 528B (16B pad kills STS conflicts)
//   within row: [lane 32][a0 a1 a2 a3 as half2]
// B buffer: [nb2 8][ks 4][lane 32][b0e b1e b0o b1o], 16KB
#define A_ROWB   528
#define A_BUFB   (8 * 4 * A_ROWB)      // 16896
#define B_BUFB   16384
#define SM_A(s)  ((uint32_t)(s) * A_BUFB)
#define SM_B(s)  ((uint32_t)(NSTAGE * A_BUFB + (s) * B_BUFB))
#define SM_TOTAL (NSTAGE * (A_BUFB + B_BUFB))   // 99840

__device__ __forceinline__ void gen_a(char* Abuf, float4 xv, int ar, int ah) {
    const int mt = ar >> 4, m = ar & 15, g = m & 7, hi = m >> 3;
    const int rot = m >> 1;
    float xs[4] = {xv.x, xv.y, xv.z, xv.w};
#pragma unroll
    for (int fl = 0; fl < 4; fl++) {
        float xc = fminf(fmaxf(xs[fl], -1.f), 1.f);
        float vals[8];
        float b = xc;
        vals[0] = b;
#pragma unroll
        for (int t = 1; t < 7; t++) { b = 2.f * xc * b - 1.f; vals[t] = b; }
        vals[7] = xc / (1.f + __expf(-xc));   // silu
        const int ks  = (ah * 4 + fl) >> 1;
        const int reg = (fl & 1) * 2 + hi;
        char* base = Abuf + (mt * 4 + ks) * A_ROWB + reg * 4;
#pragma unroll
        for (int t0 = 0; t0 < 4; t0++) {
            int tp = (t0 + rot) & 3;
            *(__half2*)(base + (g * 4 + tp) * 16) =
                __floats2half2_rn(vals[2 * tp], vals[2 * tp + 1]);
        }
    }
}

__device__ __forceinline__ void cp_b(int c, uint32_t dst, int tid, int col0) {
    const __half* src = g_W + ((size_t)c * 32 + (col0 >> 4)) * 1024 + tid * 8;
    uint32_t d = dst + (uint32_t)tid * 16;
#pragma unroll
    for (int q = 0; q < 4; q++)
        CP_ASYNC16(d + q * 4096u, src + q * 2048);
}

__device__ __forceinline__ void do_mma(const char* Asm, const char* Bsm,
                                       float acc[2][8][4], int wm, int wn, int lane) {
#pragma unroll
    for (int ks = 0; ks < 4; ks++) {
        uint4 a[2];
#pragma unroll
        for (int i = 0; i < 2; i++)
            a[i] = *(const uint4*)(Asm + ((wm * 2 + i) * 4 + ks) * A_ROWB + lane * 16);
#pragma unroll
        for (int j2 = 0; j2 < 4; j2++) {
            uint4 bb = *(const uint4*)(Bsm + (((wn * 4 + j2) * 4 + ks) * 32 + lane) * 16);
#pragma unroll
            for (int i = 0; i < 2; i++) {
                mma_fp16(acc[i][j2 * 2 + 0], a[i].x, a[i].y, a[i].z, a[i].w, bb.x, bb.y);
                mma_fp16(acc[i][j2 * 2 + 1], a[i].x, a[i].y, a[i].z, a[i].w, bb.z, bb.w);
            }
        }
    }
}

__global__ void __launch_bounds__(256, 2) kan_mma_kernel(
    const float* __restrict__ x, float* __restrict__ out)
{
    extern __shared__ char smem[];
    const uint32_t sb = smem_u32(smem);

    const int tid = threadIdx.x;
    const int wid = tid >> 5, lane = tid & 31;
    const int wm = wid & 3, wn = wid >> 2;
    const int row0 = blockIdx.x * BM;
    const int col0 = blockIdx.y * BN;

    const int ar = tid >> 1, ah = tid & 1;
    const float* xrow = x + (size_t)(row0 + ar) * IN_F + ah * 4;

    float acc[2][8][4];
#pragma unroll
    for (int i = 0; i < 2; i++)
#pragma unroll
        for (int j = 0; j < 8; j++)
#pragma unroll
            for (int q = 0; q < 4; q++) acc[i][j][q] = 0.f;

    // prologue: chunks 0 and 1 in flight
    cp_b(0, sb + SM_B(0), tid, col0); CP_COMMIT();
    cp_b(1, sb + SM_B(1), tid, col0); CP_COMMIT();
    gen_a(smem + SM_A(0), *(const float4*)xrow,       ar, ah);
    gen_a(smem + SM_A(1), *(const float4*)(xrow + 8), ar, ah);
    CP_WAIT(1);
    __syncthreads();

    for (int c = 0; c < NCHUNK; c++) {
        const int cur = c % NSTAGE;
        const bool has = (c + 2 < NCHUNK);
        const int nxt = (c + 2) % NSTAGE;
        float4 xn;
        if (has) {
            xn = *(const float4*)(xrow + (c + 2) * 8);   // early LDG
            cp_b(c + 2, sb + SM_B(nxt), tid, col0);
            CP_COMMIT();
        }
        do_mma(smem + SM_A(cur), smem + SM_B(cur), acc, wm, wn, lane);
        if (has) {
            gen_a(smem + SM_A(nxt), xn, ar, ah);
            CP_WAIT(1);
        } else {
            CP_WAIT(0);
        }
        __syncthreads();
    }

    // epilogue: add bias, float2 stores
    const int g = lane >> 2, t2 = (lane & 3) * 2;
#pragma unroll
    for (int j = 0; j < 8; j++) {
        const int col = col0 + wn * 64 + j * 8 + t2;
        const float2 bs = *(const float2*)&g_bias[col];
#pragma unroll
        for (int i = 0; i < 2; i++) {
            const int r = row0 + wm * 32 + i * 16 + g;
            float2 v0 = make_float2(acc[i][j][0] + bs.x, acc[i][j][1] + bs.y);
            float2 v1 = make_float2(acc[i][j][2] + bs.x, acc[i][j][3] + bs.y);
            *(float2*)(out + (size_t)r * OUT_F + col)       = v0;
            *(float2*)(out + (size_t)(r + 8) * OUT_F + col) = v1;
        }
    }
}

extern "C" void kernel_launch(void* const* d_in, const int* in_sizes, int n_in,
                              void* d_out, int out_size) {
    const float* x            = (const float*)d_in[0];
    const float* coeff        = (const float*)d_in[1];
    const float* scale_base   = (const float*)d_in[2];
    const float* scale_spline = (const float*)d_in[3];
    const float* base_bias    = (const float*)d_in[4];
    float* out = (float*)d_out;
    (void)in_sizes; (void)n_in; (void)out_size;

    static bool attr_set = false;
    if (!attr_set) {
        cudaFuncSetAttribute(kan_mma_kernel,
                             cudaFuncAttributeMaxDynamicSharedMemorySize, SM_TOTAL);
        attr_set = true;
    }

    dim3 eg((KTOT / 2) / 256, OUT_F);
    expand_w_kernel<<<eg, 256>>>(coeff, scale_base, scale_spline);
    bias_kernel<<<OUT_F, 256>>>(base_bias, coeff, scale_spline);

    dim3 grid(NROWS / BM, OUT_F / BN);   // 64 x 4
    kan_mma_kernel<<<grid, 256, SM_TOTAL>>>(x, out);
}

// round 7
// speedup vs baseline: 7.3189x; 1.3179x over previous
#include <cuda_runtime.h>
#include <cuda_fp16.h>
#include <cstdint>

// KANLinear as one fused fp16 mma.sync GEMM, 3-stage cp.async pipeline,
// 64x64 warp tiles (8 warps = 128x256 CTA tile) to cut LDS/HMMA ratio 3x.
// K = 4096 (constant basis j=0 folded into bias).

#define IN_F   512
#define OUT_F  512
#define NROWS  8192
#define KTOT   4096
#define BM     128
#define BN     256
#define BK     64
#define NCHUNK (KTOT / BK)     // 64
#define NSTAGE 3

// g_W in mma-B fragment order, 2 n8-groups packed per 16B for LDS.128:
//   [c][nb2][ks][lane][8 halves]; halves: {b0,b1 of even nb, b0,b1 of odd nb}
__device__ __half g_W[(size_t)NCHUNK * 32 * 1024];   // 4 MB
__device__ float  g_bias[OUT_F];

// -------- helpers --------
__device__ __forceinline__ uint32_t smem_u32(const void* p) {
    uint32_t a;
    asm("{ .reg .u64 t; cvta.to.shared.u64 t, %1; cvt.u32.u64 %0, t; }" : "=r"(a) : "l"(p));
    return a;
}
#define CP_ASYNC16(dst, src) \
    asm volatile("cp.async.cg.shared.global [%0], [%1], 16;" :: "r"(dst), "l"(src))
#define CP_COMMIT()  asm volatile("cp.async.commit_group;" ::: "memory")
#define CP_WAIT(n)   asm volatile("cp.async.wait_group %0;" :: "n"(n) : "memory")

__device__ __forceinline__ void mma_fp16(float* d, uint32_t a0, uint32_t a1,
                                         uint32_t a2, uint32_t a3,
                                         uint32_t b0, uint32_t b1) {
    asm volatile(
        "mma.sync.aligned.m16n8k16.row.col.f32.f16.f16.f32 "
        "{%0,%1,%2,%3}, {%4,%5,%6,%7}, {%8,%9}, {%0,%1,%2,%3};"
        : "+f"(d[0]), "+f"(d[1]), "+f"(d[2]), "+f"(d[3])
        : "r"(a0), "r"(a1), "r"(a2), "r"(a3), "r"(b0), "r"(b1));
}

// -------- weight expansion into fp16 fragment layout --------
__global__ void expand_w_kernel(const float* __restrict__ coeff,
                                const float* __restrict__ scale_base,
                                const float* __restrict__ scale_spline) {
    int kk2 = blockIdx.x * blockDim.x + threadIdx.x;   // 0..2047
    int o   = blockIdx.y;
    int kk  = kk2 * 2;
    int i   = kk >> 3;
    int jp  = kk & 7;                                  // even: 0,2,4,6
    const float* cb = coeff + ((size_t)o * IN_F + i) * 8;
    float ss = scale_spline[o * IN_F + i];
    float v0 = ss * cb[jp + 1];
    float v1 = (jp + 1 < 7) ? ss * cb[jp + 2] : scale_base[o * IN_F + i];
    int c = kk >> 6, k_in = kk & 63, ks = k_in >> 4, kk16 = k_in & 15;
    int rb = kk16 >> 3, t = (kk16 & 7) >> 1;
    int nb = o >> 3, g = o & 7, lane = g * 4 + t;
    size_t idx2 = ((((size_t)c * 32 + (nb >> 1)) * 4 + ks) * 32 + lane) * 4
                + (nb & 1) * 2 + rb;
    ((__half2*)g_W)[idx2] = __floats2half2_rn(v0, v1);
}

// -------- bias (base_bias rowsum + folded j=0 spline term) --------
__global__ void bias_kernel(const float* __restrict__ base_bias,
                            const float* __restrict__ coeff,
                            const float* __restrict__ scale_spline) {
    __shared__ float red[256];
    int o = blockIdx.x;
    float s = 0.f;
    for (int i = threadIdx.x; i < IN_F; i += 256) {
        s += base_bias[o * IN_F + i]
           + scale_spline[o * IN_F + i] * coeff[((size_t)o * IN_F + i) * 8 + 0];
    }
    red[threadIdx.x] = s;
    __syncthreads();
    for (int off = 128; off > 0; off >>= 1) {
        if (threadIdx.x < off) red[threadIdx.x] += red[threadIdx.x + off];
        __syncthreads();
    }
    if (threadIdx.x == 0) g_bias[o] = red[0];
}

// -------- GEMM --------
// A buffer: [mt 8][ks 4] rows of 33*16B = 528B (16B pad kills STS conflicts)
//   within row: [lane 32][a0 a1 a2 a3 as half2]
// B buffer: [nb2 16][ks 4][lane 32][b0e b1e b0o b1o], 32KB
#define A_ROWB   528
#define A_BUFB   (8 * 4 * A_ROWB)      // 16896
#define B_BUFB   32768
#define SM_A(s)  ((uint32_t)(s) * A_BUFB)
#define SM_B(s)  ((uint32_t)(NSTAGE * A_BUFB + (s) * B_BUFB))
#define SM_TOTAL (NSTAGE * (A_BUFB + B_BUFB))   // 148992

__device__ __forceinline__ void gen_a(char* Abuf, float4 xv, int ar, int ah) {
    const int mt = ar >> 4, m = ar & 15, g = m & 7, hi = m >> 3;
    const int rot = m >> 1;
    float xs[4] = {xv.x, xv.y, xv.z, xv.w};
#pragma unroll
    for (int fl = 0; fl < 4; fl++) {
        float xc = fminf(fmaxf(xs[fl], -1.f), 1.f);
        float vals[8];
        float b = xc;
        vals[0] = b;
#pragma unroll
        for (int t = 1; t < 7; t++) { b = 2.f * xc * b - 1.f; vals[t] = b; }
        vals[7] = xc / (1.f + __expf(-xc));   // silu
        const int ks  = (ah * 4 + fl) >> 1;
        const int reg = (fl & 1) * 2 + hi;
        char* base = Abuf + (mt * 4 + ks) * A_ROWB + reg * 4;
#pragma unroll
        for (int t0 = 0; t0 < 4; t0++) {
            int tp = (t0 + rot) & 3;
            *(__half2*)(base + (g * 4 + tp) * 16) =
                __floats2half2_rn(vals[2 * tp], vals[2 * tp + 1]);
        }
    }
}

__device__ __forceinline__ void cp_b(int c, uint32_t dst, int tid, int col0) {
    const __half* src = g_W + ((size_t)c * 32 + (col0 >> 4)) * 1024 + tid * 8;
    uint32_t d = dst + (uint32_t)tid * 16;
#pragma unroll
    for (int q = 0; q < 8; q++)
        CP_ASYNC16(d + q * 4096u, src + q * 2048);
}

__device__ __forceinline__ void do_mma(const char* Asm, const char* Bsm,
                                       float acc[4][8][4], int wm, int wn, int lane) {
#pragma unroll
    for (int ks = 0; ks < 4; ks++) {
        uint4 a[4];
#pragma unroll
        for (int i = 0; i < 4; i++)
            a[i] = *(const uint4*)(Asm + ((wm * 4 + i) * 4 + ks) * A_ROWB + lane * 16);
#pragma unroll
        for (int j2 = 0; j2 < 4; j2++) {
            uint4 bb = *(const uint4*)(Bsm + (((wn * 4 + j2) * 4 + ks) * 32 + lane) * 16);
#pragma unroll
            for (int i = 0; i < 4; i++) {
                mma_fp16(acc[i][j2 * 2 + 0], a[i].x, a[i].y, a[i].z, a[i].w, bb.x, bb.y);
                mma_fp16(acc[i][j2 * 2 + 1], a[i].x, a[i].y, a[i].z, a[i].w, bb.z, bb.w);
            }
        }
    }
}

__global__ void __launch_bounds__(256, 1) kan_mma_kernel(
    const float* __restrict__ x, float* __restrict__ out)
{
    extern __shared__ char smem[];
    const uint32_t sb = smem_u32(smem);

    const int tid = threadIdx.x;
    const int wid = tid >> 5, lane = tid & 31;
    const int wm = wid & 1, wn = wid >> 1;       // 2 x 4 warp grid, 64x64 tiles
    const int row0 = blockIdx.x * BM;
    const int col0 = blockIdx.y * BN;

    const int ar = tid >> 1, ah = tid & 1;
    const float* xrow = x + (size_t)(row0 + ar) * IN_F + ah * 4;

    float acc[4][8][4];
#pragma unroll
    for (int i = 0; i < 4; i++)
#pragma unroll
        for (int j = 0; j < 8; j++)
#pragma unroll
            for (int q = 0; q < 4; q++) acc[i][j][q] = 0.f;

    // prologue: chunks 0 and 1 in flight
    cp_b(0, sb + SM_B(0), tid, col0); CP_COMMIT();
    cp_b(1, sb + SM_B(1), tid, col0); CP_COMMIT();
    gen_a(smem + SM_A(0), *(const float4*)xrow,       ar, ah);
    gen_a(smem + SM_A(1), *(const float4*)(xrow + 8), ar, ah);
    CP_WAIT(1);
    __syncthreads();

    for (int c = 0; c < NCHUNK; c++) {
        const int cur = c % NSTAGE;
        const bool has = (c + 2 < NCHUNK);
        const int nxt = (c + 2) % NSTAGE;
        float4 xn;
        if (has) {
            xn = *(const float4*)(xrow + (c + 2) * 8);   // early LDG
            cp_b(c + 2, sb + SM_B(nxt), tid, col0);
            CP_COMMIT();
        }
        do_mma(smem + SM_A(cur), smem + SM_B(cur), acc, wm, wn, lane);
        if (has) {
            gen_a(smem + SM_A(nxt), xn, ar, ah);
            CP_WAIT(1);
        } else {
            CP_WAIT(0);
        }
        __syncthreads();
    }

    // epilogue: add bias, float2 stores
    const int g = lane >> 2, t2 = (lane & 3) * 2;
#pragma unroll
    for (int j = 0; j < 8; j++) {
        const int col = col0 + wn * 64 + j * 8 + t2;
        const float2 bs = *(const float2*)&g_bias[col];
#pragma unroll
        for (int i = 0; i < 4; i++) {
            const int r = row0 + wm * 64 + i * 16 + g;
            float2 v0 = make_float2(acc[i][j][0] + bs.x, acc[i][j][1] + bs.y);
            float2 v1 = make_float2(acc[i][j][2] + bs.x, acc[i][j][3] + bs.y);
            *(float2*)(out + (size_t)r * OUT_F + col)       = v0;
            *(float2*)(out + (size_t)(r + 8) * OUT_F + col) = v1;
        }
    }
}

extern "C" void kernel_launch(void* const* d_in, const int* in_sizes, int n_in,
                              void* d_out, int out_size) {
    const float* x            = (const float*)d_in[0];
    const float* coeff        = (const float*)d_in[1];
    const float* scale_base   = (const float*)d_in[2];
    const float* scale_spline = (const float*)d_in[3];
    const float* base_bias    = (const float*)d_in[4];
    float* out = (float*)d_out;
    (void)in_sizes; (void)n_in; (void)out_size;

    static bool attr_set = false;
    if (!attr_set) {
        cudaFuncSetAttribute(kan_mma_kernel,
                             cudaFuncAttributeMaxDynamicSharedMemorySize, SM_TOTAL);
        attr_set = true;
    }

    dim3 eg((KTOT / 2) / 256, OUT_F);
    expand_w_kernel<<<eg, 256>>>(coeff, scale_base, scale_spline);
    bias_kernel<<<OUT_F, 256>>>(base_bias, coeff, scale_spline);

    dim3 grid(NROWS / BM, OUT_F / BN);   // 64 x 2 = 128 CTAs
    kan_mma_kernel<<<grid, 256, SM_TOTAL>>>(x, out);
}

// round 9
// speedup vs baseline: 7.4721x; 1.0209x over previous
#include <cuda_runtime.h>
#include <cuda_fp16.h>
#include <cstdint>

// KANLinear as one fused fp16 mma.sync GEMM.
// BK=128, 2-stage cp.async pipeline, 64x64 warp tiles (8 warps = 128x256 CTA).
// K = 4096 (constant basis j=0 folded into bias). Single fused prep kernel.
// R8 fix: g_W has 32 nb2-blocks per chunk (stride 32), 4 MB total.

#define IN_F   512
#define OUT_F  512
#define NROWS  8192
#define KTOT   4096
#define BM     128
#define BN     256
#define BK     128
#define NCHUNK (KTOT / BK)     // 32
#define NSTAGE 2

// g_W in mma-B fragment order, 2 n8-groups packed per 16B for LDS.128:
//   [c 32][nb2 32][ks 8][lane 32][8 halves]   (nb2 = o>>4)
__device__ __half g_W[(size_t)NCHUNK * 32 * 8 * 32 * 8];   // 4 MB
__device__ float  g_bias[OUT_F];

// -------- helpers --------
__device__ __forceinline__ uint32_t smem_u32(const void* p) {
    uint32_t a;
    asm("{ .reg .u64 t; cvta.to.shared.u64 t, %1; cvt.u32.u64 %0, t; }" : "=r"(a) : "l"(p));
    return a;
}
#define CP_ASYNC16(dst, src) \
    asm volatile("cp.async.cg.shared.global [%0], [%1], 16;" :: "r"(dst), "l"(src))
#define CP_COMMIT()  asm volatile("cp.async.commit_group;" ::: "memory")
#define CP_WAIT(n)   asm volatile("cp.async.wait_group %0;" :: "n"(n) : "memory")

__device__ __forceinline__ void mma_fp16(float* d, uint32_t a0, uint32_t a1,
                                         uint32_t a2, uint32_t a3,
                                         uint32_t b0, uint32_t b1) {
    asm volatile(
        "mma.sync.aligned.m16n8k16.row.col.f32.f16.f16.f32 "
        "{%0,%1,%2,%3}, {%4,%5,%6,%7}, {%8,%9}, {%0,%1,%2,%3};"
        : "+f"(d[0]), "+f"(d[1]), "+f"(d[2]), "+f"(d[3])
        : "r"(a0), "r"(a1), "r"(a2), "r"(a3), "r"(b0), "r"(b1));
}

// -------- fused prep: weight expansion + bias, one block per output o --------
__global__ void __launch_bounds__(512) prep_kernel(
    const float* __restrict__ coeff,
    const float* __restrict__ scale_base,
    const float* __restrict__ scale_spline,
    const float* __restrict__ base_bias)
{
    __shared__ float red[512];
    const int o = blockIdx.x;
    const int i = threadIdx.x;                // feature

    const float4 c0 = *(const float4*)(coeff + ((size_t)o * IN_F + i) * 8);
    const float4 c1 = *(const float4*)(coeff + ((size_t)o * IN_F + i) * 8 + 4);
    const float ss = scale_spline[o * IN_F + i];
    const float sb = scale_base[o * IN_F + i];
    const float bb = base_bias[o * IN_F + i];

    float w[8];
    w[0] = ss * c0.y; w[1] = ss * c0.z; w[2] = ss * c0.w;
    w[3] = ss * c1.x; w[4] = ss * c1.y; w[5] = ss * c1.z; w[6] = ss * c1.w;
    w[7] = sb;

    // fragment placement: c = i>>4, ks = (i&15)>>1, rb = i&1
    const int c  = i >> 4;
    const int ks = (i & 15) >> 1;
    const int rb = i & 1;
    const int nb = o >> 3, g = o & 7, nb2 = nb >> 1;   // nb2 in [0,32)
    const size_t flatbase = (((size_t)c * 32 + nb2) * 8 + ks) * 32;
#pragma unroll
    for (int t = 0; t < 4; t++) {
        const int lane = g * 4 + t;
        ((__half2*)g_W)[(flatbase + lane) * 4 + (nb & 1) * 2 + rb] =
            __floats2half2_rn(w[2 * t], w[2 * t + 1]);
    }

    // bias: rowsum(base_bias) + folded j=0 spline term
    red[i] = bb + ss * c0.x;
    __syncthreads();
    for (int off = 256; off > 0; off >>= 1) {
        if (i < off) red[i] += red[i + off];
        __syncthreads();
    }
    if (i == 0) g_bias[o] = red[0];
}

// -------- GEMM --------
// A buffer: [mt 8][ks 8] rows of 33*16B = 528B (16B pad kills STS conflicts)
//   within row: [lane 32][a0 a1 a2 a3 as half2]
// B buffer: [nb2 16][ks 8][lane 32][16B] = 64KB
#define A_ROWB   528
#define A_BUFB   (8 * 8 * A_ROWB)      // 33792
#define B_BUFB   65536
#define SM_A(s)  ((uint32_t)(s) * A_BUFB)
#define SM_B(s)  ((uint32_t)(NSTAGE * A_BUFB + (s) * B_BUFB))
#define SM_TOTAL (NSTAGE * (A_BUFB + B_BUFB))   // 198656

__device__ __forceinline__ void gen_a(char* Abuf, float4 xa, float4 xb,
                                      int ar, int ah) {
    const int m = ar & 15, mt = ar >> 4, g = m & 7, hi = m >> 3;
    const int rot = m >> 1;
    float xs[8] = {xa.x, xa.y, xa.z, xa.w, xb.x, xb.y, xb.z, xb.w};
#pragma unroll
    for (int fl = 0; fl < 8; fl++) {
        float xc = fminf(fmaxf(xs[fl], -1.f), 1.f);
        float vals[8];
        float b = xc;
        vals[0] = b;
#pragma unroll
        for (int t = 1; t < 7; t++) { b = 2.f * xc * b - 1.f; vals[t] = b; }
        vals[7] = xc / (1.f + __expf(-xc));   // silu
        const int fi  = ah * 8 + fl;          // feature in chunk (0..15)
        const int ks  = fi >> 1;
        const int reg = (fi & 1) * 2 + hi;
        char* base = Abuf + (mt * 8 + ks) * A_ROWB + reg * 4;
#pragma unroll
        for (int t0 = 0; t0 < 4; t0++) {
            int tp = (t0 + rot) & 3;
            *(__half2*)(base + (g * 4 + tp) * 16) =
                __floats2half2_rn(vals[2 * tp], vals[2 * tp + 1]);
        }
    }
}

__device__ __forceinline__ void cp_b(int c, uint32_t dst, int tid, int col0) {
    // nb2 index of this CTA's first column block = col0/16; 16 nb2 blocks needed
    const __half* src = g_W + ((size_t)c * 32 + (col0 >> 4)) * 2048 + tid * 8;
    uint32_t d = dst + (uint32_t)tid * 16;
#pragma unroll
    for (int q = 0; q < 16; q++)
        CP_ASYNC16(d + q * 4096u, src + q * 2048);
}

__device__ __forceinline__ void do_mma(const char* Asm, const char* Bsm,
                                       float acc[4][8][4], int wm, int wn, int lane) {
#pragma unroll
    for (int ks = 0; ks < 8; ks++) {
        uint4 a[4];
#pragma unroll
        for (int i = 0; i < 4; i++)
            a[i] = *(const uint4*)(Asm + ((wm * 4 + i) * 8 + ks) * A_ROWB + lane * 16);
#pragma unroll
        for (int j2 = 0; j2 < 4; j2++) {
            uint4 bb = *(const uint4*)(Bsm + (((wn * 4 + j2) * 8 + ks) * 32 + lane) * 16);
#pragma unroll
            for (int i = 0; i < 4; i++) {
                mma_fp16(acc[i][j2 * 2 + 0], a[i].x, a[i].y, a[i].z, a[i].w, bb.x, bb.y);
                mma_fp16(acc[i][j2 * 2 + 1], a[i].x, a[i].y, a[i].z, a[i].w, bb.z, bb.w);
            }
        }
    }
}

__global__ void __launch_bounds__(256, 1) kan_mma_kernel(
    const float* __restrict__ x, float* __restrict__ out)
{
    extern __shared__ char smem[];
    const uint32_t sb = smem_u32(smem);

    const int tid = threadIdx.x;
    const int wid = tid >> 5, lane = tid & 31;
    const int wm = wid & 1, wn = wid >> 1;       // 2 x 4 warp grid, 64x64 tiles
    const int row0 = blockIdx.x * BM;
    const int col0 = blockIdx.y * BN;

    const int ar = tid >> 1, ah = tid & 1;
    const float* xrow = x + (size_t)(row0 + ar) * IN_F + ah * 8;

    float acc[4][8][4];
#pragma unroll
    for (int i = 0; i < 4; i++)
#pragma unroll
        for (int j = 0; j < 8; j++)
#pragma unroll
            for (int q = 0; q < 4; q++) acc[i][j][q] = 0.f;

    // prologue: chunk 0
    cp_b(0, sb + SM_B(0), tid, col0); CP_COMMIT();
    gen_a(smem + SM_A(0), *(const float4*)xrow, *(const float4*)(xrow + 4), ar, ah);
    CP_WAIT(0);
    __syncthreads();

    for (int c = 0; c < NCHUNK; c++) {
        const int cur = c & 1;
        const bool has = (c + 1 < NCHUNK);
        const int nxt = cur ^ 1;
        float4 xa, xb;
        if (has) {
            xa = *(const float4*)(xrow + (c + 1) * 16);       // early LDG
            xb = *(const float4*)(xrow + (c + 1) * 16 + 4);
            cp_b(c + 1, sb + SM_B(nxt), tid, col0);
            CP_COMMIT();
        }
        do_mma(smem + SM_A(cur), smem + SM_B(cur), acc, wm, wn, lane);
        if (has) {
            gen_a(smem + SM_A(nxt), xa, xb, ar, ah);
            CP_WAIT(0);   // cp for c+1 was hidden behind a full chunk of MMA
        }
        __syncthreads();
    }

    // epilogue: add bias, float2 stores
    const int g = lane >> 2, t2 = (lane & 3) * 2;
#pragma unroll
    for (int j = 0; j < 8; j++) {
        const int col = col0 + wn * 64 + j * 8 + t2;
        const float2 bs = *(const float2*)&g_bias[col];
#pragma unroll
        for (int i = 0; i < 4; i++) {
            const int r = row0 + wm * 64 + i * 16 + g;
            float2 v0 = make_float2(acc[i][j][0] + bs.x, acc[i][j][1] + bs.y);
            float2 v1 = make_float2(acc[i][j][2] + bs.x, acc[i][j][3] + bs.y);
            *(float2*)(out + (size_t)r * OUT_F + col)       = v0;
            *(float2*)(out + (size_t)(r + 8) * OUT_F + col) = v1;
        }
    }
}

extern "C" void kernel_launch(void* const* d_in, const int* in_sizes, int n_in,
                              void* d_out, int out_size) {
    const float* x            = (const float*)d_in[0];
    const float* coeff        = (const float*)d_in[1];
    const float* scale_base   = (const float*)d_in[2];
    const float* scale_spline = (const float*)d_in[3];
    const float* base_bias    = (const float*)d_in[4];
    float* out = (float*)d_out;
    (void)in_sizes; (void)n_in; (void)out_size;

    static bool attr_set = false;
    if (!attr_set) {
        cudaFuncSetAttribute(kan_mma_kernel,
                             cudaFuncAttributeMaxDynamicSharedMemorySize, SM_TOTAL);
        attr_set = true;
    }

    prep_kernel<<<OUT_F, 512>>>(coeff, scale_base, scale_spline, base_bias);

    dim3 grid(NROWS / BM, OUT_F / BN);   // 64 x 2 = 128 CTAs
    kan_mma_kernel<<<grid, 256, SM_TOTAL>>>(x, out);
}